// round 1
// baseline (speedup 1.0000x reference)
#include <cuda_runtime.h>
#include <cstdint>

#define N_NODE 100000
#define N_TOT  102000
#define NFEAT  256
#define NDIM   128

// ---------------------------------------------------------------------------
// zero x2/x3 regions (d_out is poisoned with 0xAA by the harness)
// ---------------------------------------------------------------------------
__global__ void zero_kernel(float* __restrict__ p, size_t n4) {
    size_t i = (size_t)blockIdx.x * blockDim.x + threadIdx.x;
    size_t stride = (size_t)gridDim.x * blockDim.x;
    float4* p4 = (float4*)p;
    for (size_t j = i; j < n4; j += stride)
        p4[j] = make_float4(0.f, 0.f, 0.f, 0.f);
}

// ---------------------------------------------------------------------------
// x1 = concat(emb_node, emb_attri) @ W1^T
// A: [N_TOT, 256] (split across two pointers), W: [128, 256], C: [N_TOT, 128]
// Both operands are K-contiguous (row-major over K), so C = A @ W^T is a
// "TN-like" layout: load K-slices of both into smem transposed.
// Tile: BM=128, BN=128 (full output width), BK=16. 256 threads, 8x8 per thread.
// ---------------------------------------------------------------------------
__global__ __launch_bounds__(256) void gemm_kernel(
    const float* __restrict__ A0,   // emb_node  [100000, 256]
    const float* __restrict__ A1,   // emb_attri [2000, 256]
    const float* __restrict__ W,    // W1 [128, 256]
    float* __restrict__ C)          // x1 [N_TOT, 128]
{
    __shared__ float As[16][128 + 4];
    __shared__ float Ws[16][128 + 4];

    const int t  = threadIdx.x;
    const int tx = t & 15;          // output col group
    const int ty = t >> 4;          // output row group
    const int blockRow = blockIdx.x * 128;

    float acc[8][8];
#pragma unroll
    for (int i = 0; i < 8; i++)
#pragma unroll
        for (int j = 0; j < 8; j++) acc[i][j] = 0.f;

    for (int kk = 0; kk < NFEAT; kk += 16) {
        // Load tiles: 128 rows x 16 k = 512 float4 each; 2 per thread.
#pragma unroll
        for (int l = 0; l < 2; l++) {
            int idx = t + l * 256;
            int r   = idx >> 2;           // 0..127
            int kq  = (idx & 3) << 2;     // 0,4,8,12

            // A tile (guard rows beyond N_TOT, select node/attri table)
            int grow = blockRow + r;
            float4 v = make_float4(0.f, 0.f, 0.f, 0.f);
            if (grow < N_TOT) {
                const float* src = (grow < N_NODE)
                    ? (A0 + (size_t)grow * NFEAT)
                    : (A1 + (size_t)(grow - N_NODE) * NFEAT);
                v = *(const float4*)(src + kk + kq);
            }
            As[kq + 0][r] = v.x; As[kq + 1][r] = v.y;
            As[kq + 2][r] = v.z; As[kq + 3][r] = v.w;

            // W tile (all 128 rows valid)
            float4 w = *(const float4*)(W + (size_t)r * NFEAT + kk + kq);
            Ws[kq + 0][r] = w.x; Ws[kq + 1][r] = w.y;
            Ws[kq + 2][r] = w.z; Ws[kq + 3][r] = w.w;
        }
        __syncthreads();

#pragma unroll
        for (int k = 0; k < 16; k++) {
            float a[8], b[8];
#pragma unroll
            for (int i = 0; i < 4; i++) {
                a[i]     = As[k][ty * 4 + i];
                a[i + 4] = As[k][64 + ty * 4 + i];
                b[i]     = Ws[k][tx * 4 + i];
                b[i + 4] = Ws[k][64 + tx * 4 + i];
            }
#pragma unroll
            for (int i = 0; i < 8; i++)
#pragma unroll
                for (int j = 0; j < 8; j++)
                    acc[i][j] = fmaf(a[i], b[j], acc[i][j]);
        }
        __syncthreads();
    }

    // Epilogue
#pragma unroll
    for (int i = 0; i < 8; i++) {
        int rloc = (i < 4) ? (ty * 4 + i) : (64 + ty * 4 + (i - 4));
        int r = blockRow + rloc;
        if (r < N_TOT) {
            float* crow = C + (size_t)r * NDIM;
#pragma unroll
            for (int j = 0; j < 8; j++) {
                int cloc = (j < 4) ? (tx * 4 + j) : (64 + tx * 4 + (j - 4));
                crow[cloc] = acc[i][j];
            }
        }
    }
}

// ---------------------------------------------------------------------------
// SpMM scatter: out[row[e], :] += val[e] * x1[col[e], :]
// One warp per edge: 32 lanes x float4 = 128 floats. Vector reduction
// (red.global.add.v4.f32) to quarter the atomic-op count.
// ---------------------------------------------------------------------------
__global__ __launch_bounds__(256) void scatter_kernel(
    const float* __restrict__ x1,
    const int*   __restrict__ erow,
    const int*   __restrict__ ecol,
    const float* __restrict__ eval,
    float* __restrict__ out,
    int E)
{
    int gw = (int)(((size_t)blockIdx.x * blockDim.x + threadIdx.x) >> 5);
    if (gw >= E) return;
    int lane = threadIdx.x & 31;

    int   r = __ldg(erow + gw);
    int   c = __ldg(ecol + gw);
    float v = __ldg(eval + gw);

    float4 p = ((const float4*)(x1 + (size_t)c * NDIM))[lane];
    float* dst = out + (size_t)r * NDIM + lane * 4;

    asm volatile("red.global.add.v4.f32 [%0], {%1, %2, %3, %4};"
                 :: "l"(dst), "f"(p.x * v), "f"(p.y * v), "f"(p.z * v), "f"(p.w * v)
                 : "memory");
}

// ---------------------------------------------------------------------------
extern "C" void kernel_launch(void* const* d_in, const int* in_sizes, int n_in,
                              void* d_out, int out_size)
{
    const float* emb_node  = (const float*)d_in[0];
    const float* emb_attri = (const float*)d_in[1];
    const float* W1        = (const float*)d_in[2];
    const int*   adj_row   = (const int*)d_in[3];
    const int*   adj_col   = (const int*)d_in[4];
    const float* adj_val   = (const float*)d_in[5];
    const int*   adj2_row  = (const int*)d_in[6];
    const int*   adj2_col  = (const int*)d_in[7];
    const float* adj2_val  = (const float*)d_in[8];

    float* out = (float*)d_out;
    float* x1 = out;
    float* x2 = out + (size_t)N_TOT * NDIM;
    float* x3 = x2  + (size_t)N_TOT * NDIM;

    const int E = in_sizes[3];

    // zero x2 and x3 (contiguous): 2 * N_TOT * NDIM floats
    size_t nzero4 = ((size_t)2 * N_TOT * NDIM) >> 2;
    zero_kernel<<<2048, 256>>>(x2, nzero4);

    // x1 = x0 @ W1^T
    gemm_kernel<<<(N_TOT + 127) / 128, 256>>>(emb_node, emb_attri, W1, x1);

    // scatter both adjacencies
    long long total_threads = (long long)E * 32;
    int blocks = (int)((total_threads + 255) / 256);
    scatter_kernel<<<blocks, 256>>>(x1, adj_row,  adj_col,  adj_val,  x2, E);
    scatter_kernel<<<blocks, 256>>>(x1, adj2_row, adj2_col, adj2_val, x3, E);
}

// round 2
// speedup vs baseline: 1.3226x; 1.3226x over previous
#include <cuda_runtime.h>
#include <cstdint>

#define N_NODE 100000
#define N_TOT  102000
#define NFEAT  256
#define NDIM   128

// ---------------------------------------------------------------------------
// zero x2/x3 regions (d_out is poisoned with 0xAA by the harness)
// ---------------------------------------------------------------------------
__global__ void zero_kernel(float* __restrict__ p, size_t n4) {
    size_t i = (size_t)blockIdx.x * blockDim.x + threadIdx.x;
    size_t stride = (size_t)gridDim.x * blockDim.x;
    float4* p4 = (float4*)p;
    for (size_t j = i; j < n4; j += stride)
        p4[j] = make_float4(0.f, 0.f, 0.f, 0.f);
}

// ---------------------------------------------------------------------------
// x1 = concat(emb_node, emb_attri) @ W1^T
// Tile: BM=128, BN=128 (full output width), BK=16. 256 threads, 8x8/thread.
// ---------------------------------------------------------------------------
__global__ __launch_bounds__(256) void gemm_kernel(
    const float* __restrict__ A0,   // emb_node  [100000, 256]
    const float* __restrict__ A1,   // emb_attri [2000, 256]
    const float* __restrict__ W,    // W1 [128, 256]
    float* __restrict__ C)          // x1 [N_TOT, 128]
{
    __shared__ float As[16][128 + 4];
    __shared__ float Ws[16][128 + 4];

    const int t  = threadIdx.x;
    const int tx = t & 15;          // output col group
    const int ty = t >> 4;          // output row group
    const int blockRow = blockIdx.x * 128;

    float acc[8][8];
#pragma unroll
    for (int i = 0; i < 8; i++)
#pragma unroll
        for (int j = 0; j < 8; j++) acc[i][j] = 0.f;

    for (int kk = 0; kk < NFEAT; kk += 16) {
#pragma unroll
        for (int l = 0; l < 2; l++) {
            int idx = t + l * 256;
            int r   = idx >> 2;           // 0..127
            int kq  = (idx & 3) << 2;     // 0,4,8,12

            int grow = blockRow + r;
            float4 v = make_float4(0.f, 0.f, 0.f, 0.f);
            if (grow < N_TOT) {
                const float* src = (grow < N_NODE)
                    ? (A0 + (size_t)grow * NFEAT)
                    : (A1 + (size_t)(grow - N_NODE) * NFEAT);
                v = *(const float4*)(src + kk + kq);
            }
            As[kq + 0][r] = v.x; As[kq + 1][r] = v.y;
            As[kq + 2][r] = v.z; As[kq + 3][r] = v.w;

            float4 w = *(const float4*)(W + (size_t)r * NFEAT + kk + kq);
            Ws[kq + 0][r] = w.x; Ws[kq + 1][r] = w.y;
            Ws[kq + 2][r] = w.z; Ws[kq + 3][r] = w.w;
        }
        __syncthreads();

#pragma unroll
        for (int k = 0; k < 16; k++) {
            float a[8], b[8];
#pragma unroll
            for (int i = 0; i < 4; i++) {
                a[i]     = As[k][ty * 4 + i];
                a[i + 4] = As[k][64 + ty * 4 + i];
                b[i]     = Ws[k][tx * 4 + i];
                b[i + 4] = Ws[k][64 + tx * 4 + i];
            }
#pragma unroll
            for (int i = 0; i < 8; i++)
#pragma unroll
                for (int j = 0; j < 8; j++)
                    acc[i][j] = fmaf(a[i], b[j], acc[i][j]);
        }
        __syncthreads();
    }

#pragma unroll
    for (int i = 0; i < 8; i++) {
        int rloc = (i < 4) ? (ty * 4 + i) : (64 + ty * 4 + (i - 4));
        int r = blockRow + rloc;
        if (r < N_TOT) {
            float* crow = C + (size_t)r * NDIM;
#pragma unroll
            for (int j = 0; j < 8; j++) {
                int cloc = (j < 4) ? (tx * 4 + j) : (64 + tx * 4 + (j - 4));
                crow[cloc] = acc[i][j];
            }
        }
    }
}

// ---------------------------------------------------------------------------
// SpMM scatter, both adjacencies in one launch.
// EPW=4 edges per warp: 4 independent gathers in flight before the dependent
// reductions (MLP=4), vectorized edge-metadata loads (int4/float4 broadcast).
// ---------------------------------------------------------------------------
#define EPW 4

__global__ __launch_bounds__(256) void scatter2_kernel(
    const float* __restrict__ x1,
    const int*   __restrict__ erow1,
    const int*   __restrict__ ecol1,
    const float* __restrict__ eval1,
    const int*   __restrict__ erow2,
    const int*   __restrict__ ecol2,
    const float* __restrict__ eval2,
    float* __restrict__ x2,
    float* __restrict__ x3,
    int E)
{
    const int warpsPerAdj = (E + EPW - 1) / EPW;
    int gw = (int)(((size_t)blockIdx.x * blockDim.x + threadIdx.x) >> 5);
    const int lane = threadIdx.x & 31;

    const int*   erow;
    const int*   ecol;
    const float* eval;
    float*       out;
    if (gw < warpsPerAdj) {
        erow = erow1; ecol = ecol1; eval = eval1; out = x2;
    } else {
        gw -= warpsPerAdj;
        if (gw >= warpsPerAdj) return;
        erow = erow2; ecol = ecol2; eval = eval2; out = x3;
    }

    const int e0 = gw * EPW;
    int rr[EPW], cc[EPW];
    float vv[EPW];
    int n;
    if (e0 + EPW <= E) {
        n = EPW;
        int4   r4 = *(const int4*)(erow + e0);
        int4   c4 = *(const int4*)(ecol + e0);
        float4 v4 = *(const float4*)(eval + e0);
        rr[0] = r4.x; rr[1] = r4.y; rr[2] = r4.z; rr[3] = r4.w;
        cc[0] = c4.x; cc[1] = c4.y; cc[2] = c4.z; cc[3] = c4.w;
        vv[0] = v4.x; vv[1] = v4.y; vv[2] = v4.z; vv[3] = v4.w;
    } else {
        n = E - e0;
#pragma unroll
        for (int i = 0; i < EPW; i++) {
            if (i < n) {
                rr[i] = __ldg(erow + e0 + i);
                cc[i] = __ldg(ecol + e0 + i);
                vv[i] = __ldg(eval + e0 + i);
            }
        }
    }

    // Phase 1: issue all gathers (independent -> MLP=EPW)
    float4 p[EPW];
#pragma unroll
    for (int i = 0; i < EPW; i++)
        if (i < n)
            p[i] = ((const float4*)(x1 + (size_t)cc[i] * NDIM))[lane];

    // Phase 2: scale + vector reductions
#pragma unroll
    for (int i = 0; i < EPW; i++) {
        if (i < n) {
            float* dst = out + (size_t)rr[i] * NDIM + lane * 4;
            asm volatile("red.global.add.v4.f32 [%0], {%1, %2, %3, %4};"
                         :: "l"(dst),
                            "f"(p[i].x * vv[i]), "f"(p[i].y * vv[i]),
                            "f"(p[i].z * vv[i]), "f"(p[i].w * vv[i])
                         : "memory");
        }
    }
}

// ---------------------------------------------------------------------------
extern "C" void kernel_launch(void* const* d_in, const int* in_sizes, int n_in,
                              void* d_out, int out_size)
{
    const float* emb_node  = (const float*)d_in[0];
    const float* emb_attri = (const float*)d_in[1];
    const float* W1        = (const float*)d_in[2];
    const int*   adj_row   = (const int*)d_in[3];
    const int*   adj_col   = (const int*)d_in[4];
    const float* adj_val   = (const float*)d_in[5];
    const int*   adj2_row  = (const int*)d_in[6];
    const int*   adj2_col  = (const int*)d_in[7];
    const float* adj2_val  = (const float*)d_in[8];

    float* out = (float*)d_out;
    float* x1 = out;
    float* x2 = out + (size_t)N_TOT * NDIM;
    float* x3 = x2  + (size_t)N_TOT * NDIM;

    const int E = in_sizes[3];

    // zero x2 and x3 (contiguous)
    size_t nzero4 = ((size_t)2 * N_TOT * NDIM) >> 2;
    zero_kernel<<<2048, 256>>>(x2, nzero4);

    // x1 = x0 @ W1^T
    gemm_kernel<<<(N_TOT + 127) / 128, 256>>>(emb_node, emb_attri, W1, x1);

    // both scatters in one launch
    const int warpsPerAdj = (E + EPW - 1) / EPW;
    long long totalThreads = (long long)warpsPerAdj * 2 * 32;
    int blocks = (int)((totalThreads + 255) / 256);
    scatter2_kernel<<<blocks, 256>>>(x1, adj_row,  adj_col,  adj_val,
                                         adj2_row, adj2_col, adj2_val,
                                     x2, x3, E);
}